// round 14
// baseline (speedup 1.0000x reference)
#include <cuda_runtime.h>

// ---------------------------------------------------------------------------
// PCELayer R14: legacy mma.sync tf32 (tcgen05 unavailable: toolchain targets
// plain sm_100).  vs R12: 128-thread CTAs, warp tile 64co x (32x x 2y) px ->
// A-fragment reuse across 8 n-tiles: 1.0 smem wavefront per MMA (was 1.5).
// ---------------------------------------------------------------------------

#define kB    8
#define kCIN  64
#define kCOUT 128
#define kH    128
#define kW    128
#define kE    8
#define kHp   8
#define kWp   8
#define kHID  128
#define kGCH  80
#define kG    8

// scratch
__device__ float    g_h1[kB * kCOUT * kH * kW];
__device__ float    g_xtf[kB * kCIN * kH * kW];
__device__ unsigned g_W1p[kE * kCIN * 9 * 128];
__device__ unsigned g_W2p[kE * kCOUT * 9 * 128];
__device__ unsigned g_Wrp[kE * (kCIN / 8) * 1024];
__device__ float    g_gates[kB * kHp * kWp * kE];
__device__ double   g_part[kB * kG * 32 * 2];
__device__ float    g_stats[kB * kG * 2];

// ---------------------------------------------------------------------------
// helpers
// ---------------------------------------------------------------------------
__device__ __forceinline__ unsigned f2tf(float f) {
    unsigned u;
    asm("cvt.rna.tf32.f32 %0, %1;" : "=r"(u) : "f"(f));
    return u;
}

__device__ __forceinline__ void mma_tf32(float acc[4], unsigned a0, unsigned a1,
                                         unsigned a2, unsigned a3,
                                         unsigned b0, unsigned b1) {
    asm volatile(
        "mma.sync.aligned.m16n8k8.row.col.f32.tf32.tf32.f32 "
        "{%0,%1,%2,%3}, {%4,%5,%6,%7}, {%8,%9}, {%0,%1,%2,%3};\n"
        : "+f"(acc[0]), "+f"(acc[1]), "+f"(acc[2]), "+f"(acc[3])
        : "r"(a0), "r"(a1), "r"(a2), "r"(a3), "r"(b0), "r"(b1));
}

__device__ __forceinline__ void cp_async16(unsigned* dst, const void* src) {
    unsigned d = (unsigned)__cvta_generic_to_shared(dst);
    asm volatile("cp.async.cg.shared.global [%0], [%1], 16;" :: "r"(d), "l"(src));
}
__device__ __forceinline__ void cp_async4z(unsigned* dst, const void* src, bool ok) {
    unsigned d = (unsigned)__cvta_generic_to_shared(dst);
    int sz = ok ? 4 : 0;
    asm volatile("cp.async.ca.shared.global [%0], [%1], 4, %2;" :: "r"(d), "l"(src), "r"(sz));
}
__device__ __forceinline__ void cp_commit() {
    asm volatile("cp.async.commit_group;");
}
template <int N>
__device__ __forceinline__ void cp_wait() {
    asm volatile("cp.async.wait_group %0;" :: "n"(N));
}

// ---------------------------------------------------------------------------
// Prep: x round + all weight permutes (same layouts as R12).
// 3x3 layout per expert: [chunk][tap 9][ct 8][lane 32][j 4]
//   co = ct*16 + (lane>>2) + (j&1)*8 ; ci = chunk*8 + (lane&3) + (j>>1)*4
// ---------------------------------------------------------------------------
__global__ void prep_x_kernel(const float* __restrict__ x) {
    int idx = blockIdx.x * 256 + threadIdx.x;
    const float4* in = reinterpret_cast<const float4*>(x);
    float4 v = in[idx];
    float4 o;
    o.x = __uint_as_float(f2tf(v.x));
    o.y = __uint_as_float(f2tf(v.y));
    o.z = __uint_as_float(f2tf(v.z));
    o.w = __uint_as_float(f2tf(v.w));
    reinterpret_cast<float4*>(g_xtf)[idx] = o;
}

__device__ __forceinline__ unsigned perm_w3x3(const float* W, int CIN, int idx) {
    int perE = CIN * 1152;
    int e = idx / perE;
    int r = idx - e * perE;
    int chunk = r / 9216;
    int r2 = r - chunk * 9216;
    int tap = r2 >> 10;
    int r3 = r2 & 1023;
    int ct = r3 >> 7;
    int lane = (r3 >> 2) & 31;
    int j = r3 & 3;
    int co = ct * 16 + (lane >> 2) + (j & 1) * 8;
    int ci = chunk * 8 + (lane & 3) + (j >> 1) * 4;
    return f2tf(W[((size_t)(e * 128 + co) * CIN + ci) * 9 + tap]);
}

__global__ void prep_w_all(const float* __restrict__ W1,
                           const float* __restrict__ W2,
                           const float* __restrict__ Wr)
{
    const int N1 = kE * kCIN  * 9 * 128;
    const int N2 = kE * kCOUT * 9 * 128;
    const int N3 = kE * 8192;
    for (int idx = blockIdx.x * 256 + threadIdx.x; idx < N1 + N2 + N3;
         idx += gridDim.x * 256) {
        if (idx < N1) {
            g_W1p[idx] = perm_w3x3(W1, kCIN, idx);
        } else if (idx < N1 + N2) {
            int i2 = idx - N1;
            g_W2p[i2] = perm_w3x3(W2, kCOUT, i2);
        } else {
            int i3 = idx - N1 - N2;
            int e = i3 >> 13;
            int r = i3 & 8191;
            int chunk = r >> 10;
            int r3 = r & 1023;
            int ct = r3 >> 7;
            int lane = (r3 >> 2) & 31;
            int j = r3 & 3;
            int co = ct * 16 + (lane >> 2) + (j & 1) * 8;
            int ci = chunk * 8 + (lane & 3) + (j >> 1) * 4;
            g_Wrp[i3] = f2tf(Wr[(e * 128 + co) * kCIN + ci]);
        }
    }
}

// ---------------------------------------------------------------------------
// Router
// ---------------------------------------------------------------------------
__global__ void router_kernel(const float* __restrict__ x,
                              const float* __restrict__ Rw1,
                              const float* __restrict__ Rb1,
                              const float* __restrict__ Rw2,
                              const float* __restrict__ Rb2)
{
    __shared__ float s_g[kGCH];
    __shared__ float s_h[kHID];
    __shared__ float s_l[kE];

    const int blk = blockIdx.x;
    const int b  = blk >> 6;
    const int hp = (blk >> 3) & 7;
    const int wp = blk & 7;
    const int t  = threadIdx.x;

    if (t < 64) {
        const float* xp = x + ((b * kCIN + t) * kH + hp * 16) * kW + wp * 16;
        float s = 0.f;
        for (int r = 0; r < 16; r++) {
            const float4* rp = reinterpret_cast<const float4*>(xp + r * kW);
            #pragma unroll
            for (int c4 = 0; c4 < 4; c4++) {
                float4 v = rp[c4];
                s += v.x + v.y + v.z + v.w;
            }
        }
        s_g[t] = s * (1.f / 256.f);
    } else if (t < 80) {
        int k = t - 64;
        int f = k & 3;
        int kind = k >> 2;
        float freq = (float)(1 << f) * 3.14159265358979323846f;
        float coord = (kind < 2) ? ((hp + 0.5f) / 8.0f) : ((wp + 0.5f) / 8.0f);
        float a = coord * freq;
        s_g[t] = (kind & 1) ? cosf(a) : sinf(a);
    }
    __syncthreads();

    {
        float hsum = Rb1[t];
        #pragma unroll 4
        for (int c = 0; c < kGCH; c++) hsum = fmaf(s_g[c], Rw1[c * kHID + t], hsum);
        s_h[t] = fmaxf(hsum, 0.f);
    }
    __syncthreads();

    if (t < kE) {
        float l = Rb2[t];
        #pragma unroll 4
        for (int d = 0; d < kHID; d++) l = fmaf(s_h[d], Rw2[d * kE + t], l);
        s_l[t] = l;
    }
    __syncthreads();

    if (t == 0) {
        float m = s_l[0];
        #pragma unroll
        for (int e = 1; e < kE; e++) m = fmaxf(m, s_l[e]);
        float ex[kE];
        float ssum = 0.f;
        #pragma unroll
        for (int e = 0; e < kE; e++) { ex[e] = expf(s_l[e] - m); ssum += ex[e]; }
        float inv = 1.f / ssum;
        #pragma unroll
        for (int e = 0; e < kE; e++)
            g_gates[((b * kHp + hp) * kWp + wp) * kE + e] = ex[e] * inv;
    }
}

// ---------------------------------------------------------------------------
// Conv kernel (pipelined, double-buffered).
// CTA: 128co x (32x x 4y) px, 128 threads = 4 warps.
// warp: wm = w>>1 (64 co), wq = w&1 -> rows {wq*2, wq*2+1}.
// Warp tile 64co x 64px: per tap 4 LDS.128 A + 8 LDS.64 B -> 32 MMA (1.0 wf/MMA).
// Input smem: uint2 planes [cp=ci&3][row 6][col 34], plane stride 204 uint2.
// ---------------------------------------------------------------------------
#define W_WORDS   9216
#define IN_WORDS  1632
#define BUF_WORDS (W_WORDS + IN_WORDS)   // 10848 words = 43392 B
#define CTA_THREADS 128

template <int NMAIN, bool C2>
__global__ void __launch_bounds__(CTA_THREADS)
conv_tc(const float* __restrict__ smain,
        const unsigned* __restrict__ wmain,
        const unsigned* __restrict__ wres,
        const float* __restrict__ bias,
        const float* __restrict__ bias2,
        int e, int is_first, float* __restrict__ out)
{
    extern __shared__ unsigned dyn[];

    const int t = threadIdx.x;
    const int lane = t & 31, w = t >> 5;
    const int g = lane >> 2, tin = lane & 3;
    const int wm = w >> 1, wq = w & 1;
    const int gx0 = blockIdx.x * 32, gy0 = blockIdx.y * 4;
    const int b = blockIdx.z;

    const int CINM = NMAIN * 8;
    const int njobs = NMAIN + (C2 ? kCIN / 8 : 0);

    // -------- staging --------
    auto issue = [&](int job, int bufi) {
        unsigned* bw  = dyn + bufi * BUF_WORDS;
        unsigned* bin = bw + W_WORDS;
        const float* src; int ci0, cin_src; const unsigned* wsrc; int wn;
        if (job < NMAIN) {
            src = smain; ci0 = job * 8; cin_src = CINM;
            wsrc = wmain + job * W_WORDS; wn = W_WORDS;
        } else {
            src = g_xtf; ci0 = (job - NMAIN) * 8; cin_src = kCIN;
            wsrc = wres + (job - NMAIN) * 1024; wn = 1024;
        }
        for (int i = t; i < wn / 4; i += CTA_THREADS)
            cp_async16(bw + i * 4, wsrc + i * 4);
        // halo rows gy0-1 .. gy0+4; (ci,row,col) -> word (ci&3)*408 + rem*2 + (ci>>2)
        for (int idx = t; idx < 8 * 6 * 34; idx += CTA_THREADS) {
            int ci  = idx / 204;
            int rem = idx - ci * 204;
            int row = rem / 34;
            int col = rem - row * 34;
            int gy = gy0 + row - 1;
            int gx = gx0 + col - 1;
            bool ok = ((unsigned)gy < (unsigned)kH) && ((unsigned)gx < (unsigned)kW);
            const float* sp = ok
                ? src + ((size_t)(b * cin_src + ci0 + ci) * kH + gy) * kW + gx
                : src;
            cp_async4z(bin + (ci & 3) * 408 + rem * 2 + (ci >> 2), sp, ok);
        }
        cp_commit();
    };

    // -------- compute --------
    float acc[2][4][4][4];   // [ro row][mt co-tile][nt][frag]
    #pragma unroll
    for (int ro = 0; ro < 2; ro++)
        #pragma unroll
        for (int mt = 0; mt < 4; mt++)
            #pragma unroll
            for (int nt = 0; nt < 4; nt++)
                #pragma unroll
                for (int u = 0; u < 4; u++) acc[ro][mt][nt][u] = 0.f;

    auto do_mma = [&](int job, int bufi) {
        unsigned* bw = dyn + bufi * BUF_WORDS;
        const uint4* aw = reinterpret_cast<const uint4*>(bw);
        const uint2* sinp = reinterpret_cast<const uint2*>(bw + W_WORDS);
        if (job < NMAIN) {
            #pragma unroll
            for (int tap = 0; tap < 9; tap++) {
                const int dy = tap / 3, dx = tap % 3;
                uint4 A[4];
                #pragma unroll
                for (int mt = 0; mt < 4; mt++)
                    A[mt] = aw[(tap * 8 + wm * 4 + mt) * 32 + lane];
                #pragma unroll
                for (int ro = 0; ro < 2; ro++) {
                    const int row = wq * 2 + ro + dy;
                    const uint2* rp = sinp + tin * 204 + row * 34 + dx + g;
                    #pragma unroll
                    for (int nt = 0; nt < 4; nt++) {
                        uint2 b01 = rp[nt * 8];
                        #pragma unroll
                        for (int mt = 0; mt < 4; mt++)
                            mma_tf32(acc[ro][mt][nt], A[mt].x, A[mt].y, A[mt].z,
                                     A[mt].w, b01.x, b01.y);
                    }
                }
            }
        } else {
            uint4 A[4];
            #pragma unroll
            for (int mt = 0; mt < 4; mt++)
                A[mt] = aw[(wm * 4 + mt) * 32 + lane];
            #pragma unroll
            for (int ro = 0; ro < 2; ro++) {
                const int row = wq * 2 + ro + 1;
                const uint2* rp = sinp + tin * 204 + row * 34 + 1 + g;
                #pragma unroll
                for (int nt = 0; nt < 4; nt++) {
                    uint2 b01 = rp[nt * 8];
                    #pragma unroll
                    for (int mt = 0; mt < 4; mt++)
                        mma_tf32(acc[ro][mt][nt], A[mt].x, A[mt].y, A[mt].z,
                                 A[mt].w, b01.x, b01.y);
                }
            }
        }
    };

    // -------- pipeline --------
    issue(0, 0);
    for (int j = 0; j < njobs; j++) {
        if (j + 1 < njobs) {
            issue(j + 1, (j + 1) & 1);
            cp_wait<1>();
        } else {
            cp_wait<0>();
        }
        __syncthreads();
        do_mma(j, j & 1);
        __syncthreads();
    }

    // -------- epilogue --------
    #pragma unroll
    for (int ro = 0; ro < 2; ro++) {
        const int y = gy0 + wq * 2 + ro;
        if (!C2) {
            #pragma unroll
            for (int mt = 0; mt < 4; mt++) {
                int co0 = wm * 64 + mt * 16 + g;
                float bb0 = bias[co0], bb1 = bias[co0 + 8];
                #pragma unroll
                for (int nt = 0; nt < 4; nt++) {
                    int gx = gx0 + nt * 8 + tin * 2;
                    float2 o0, o1;
                    o0.x = __uint_as_float(f2tf(fmaxf(acc[ro][mt][nt][0] + bb0, 0.f)));
                    o0.y = __uint_as_float(f2tf(fmaxf(acc[ro][mt][nt][1] + bb0, 0.f)));
                    o1.x = __uint_as_float(f2tf(fmaxf(acc[ro][mt][nt][2] + bb1, 0.f)));
                    o1.y = __uint_as_float(f2tf(fmaxf(acc[ro][mt][nt][3] + bb1, 0.f)));
                    *reinterpret_cast<float2*>(&g_h1[((b * kCOUT + co0    ) * kH + y) * kW + gx]) = o0;
                    *reinterpret_cast<float2*>(&g_h1[((b * kCOUT + co0 + 8) * kH + y) * kW + gx]) = o1;
                }
            }
        } else {
            const int prow = (b * kHp + (y >> 4)) * kWp;
            const float gateL = g_gates[(prow + ((gx0      ) >> 4)) * kE + e];
            const float gateR = g_gates[(prow + ((gx0 + 16) >> 4)) * kE + e];
            #pragma unroll
            for (int mt = 0; mt < 4; mt++) {
                int co0 = wm * 64 + mt * 16 + g;
                float bb0 = bias[co0] + bias2[co0];
                float bb1 = bias[co0 + 8] + bias2[co0 + 8];
                #pragma unroll
                for (int nt = 0; nt < 4; nt++) {
                    const float gate = (nt < 2) ? gateL : gateR;
                    int gx = gx0 + nt * 8 + tin * 2;
                    float2 o0, o1;
                    o0.x = fmaxf(acc[ro][mt][nt][0] + bb0, 0.f) * gate;
                    o0.y = fmaxf(acc[ro][mt][nt][1] + bb0, 0.f) * gate;
                    o1.x = fmaxf(acc[ro][mt][nt][2] + bb1, 0.f) * gate;
                    o1.y = fmaxf(acc[ro][mt][nt][3] + bb1, 0.f) * gate;
                    float2* p0 = reinterpret_cast<float2*>(&out[((b * kCOUT + co0    ) * kH + y) * kW + gx]);
                    float2* p1 = reinterpret_cast<float2*>(&out[((b * kCOUT + co0 + 8) * kH + y) * kW + gx]);
                    if (!is_first) {
                        float2 v0 = *p0, v1 = *p1;
                        o0.x += v0.x; o0.y += v0.y;
                        o1.x += v1.x; o1.y += v1.y;
                    }
                    *p0 = o0;
                    *p1 = o1;
                }
            }
        }
    }
}

// ---------------------------------------------------------------------------
// GroupNorm
// ---------------------------------------------------------------------------
__global__ void gn_partial_kernel(const float* __restrict__ y)
{
    const int bid = blockIdx.x;
    const int bg = bid >> 5, sl = bid & 31;
    const int t = threadIdx.x;
    const float4* p = reinterpret_cast<const float4*>(
        y + (size_t)bg * ((kCOUT / kG) * kH * kW) + sl * 8192);

    double s = 0.0, q = 0.0;
    for (int i = t; i < 2048; i += 256) {
        float4 v = p[i];
        s += (double)v.x + (double)v.y + (double)v.z + (double)v.w;
        q += (double)v.x * v.x + (double)v.y * v.y +
             (double)v.z * v.z + (double)v.w * v.w;
    }
    __shared__ double sh_s[256], sh_q[256];
    sh_s[t] = s; sh_q[t] = q;
    __syncthreads();
    for (int off = 128; off > 0; off >>= 1) {
        if (t < off) { sh_s[t] += sh_s[t + off]; sh_q[t] += sh_q[t + off]; }
        __syncthreads();
    }
    if (t == 0) {
        g_part[(bg * 32 + sl) * 2 + 0] = sh_s[0];
        g_part[(bg * 32 + sl) * 2 + 1] = sh_q[0];
    }
}

__global__ void gn_final_kernel()
{
    const int bg = blockIdx.x;
    const int t = threadIdx.x;
    double s = g_part[(bg * 32 + t) * 2 + 0];
    double q = g_part[(bg * 32 + t) * 2 + 1];
    #pragma unroll
    for (int off = 16; off > 0; off >>= 1) {
        s += __shfl_down_sync(0xffffffffu, s, off);
        q += __shfl_down_sync(0xffffffffu, q, off);
    }
    if (t == 0) {
        const double N = (double)((kCOUT / kG) * kH * kW);
        double mean = s / N;
        double var  = q / N - mean * mean;
        g_stats[bg * 2 + 0] = (float)mean;
        g_stats[bg * 2 + 1] = (float)(1.0 / sqrt(var + 1e-5));
    }
}

__global__ void gn_apply_kernel(float* __restrict__ y,
                                const float* __restrict__ gamma,
                                const float* __restrict__ beta)
{
    const int idx4 = blockIdx.x * 256 + threadIdx.x;
    const int idx = idx4 * 4;
    const int c = (idx >> 14) & 127;
    const int bg = idx >> 18;
    const float mean = g_stats[bg * 2 + 0];
    const float rstd = g_stats[bg * 2 + 1];
    const float ga = gamma[c] * rstd;
    const float be = beta[c] - mean * ga;
    float4 v = *reinterpret_cast<float4*>(&y[idx]);
    v.x = v.x * ga + be;
    v.y = v.y * ga + be;
    v.z = v.z * ga + be;
    v.w = v.w * ga + be;
    *reinterpret_cast<float4*>(&y[idx]) = v;
}

// ---------------------------------------------------------------------------
// Launch
// ---------------------------------------------------------------------------
extern "C" void kernel_launch(void* const* d_in, const int* in_sizes, int n_in,
                              void* d_out, int out_size)
{
    const float* x     = (const float*)d_in[0];
    const float* W1    = (const float*)d_in[1];
    const float* b1    = (const float*)d_in[2];
    const float* W2    = (const float*)d_in[3];
    const float* b2    = (const float*)d_in[4];
    const float* Wr    = (const float*)d_in[5];
    const float* br    = (const float*)d_in[6];
    const float* Rw1   = (const float*)d_in[7];
    const float* Rb1   = (const float*)d_in[8];
    const float* Rw2   = (const float*)d_in[9];
    const float* Rb2   = (const float*)d_in[10];
    const float* gamma = (const float*)d_in[11];
    const float* beta  = (const float*)d_in[12];
    float* out = (float*)d_out;

    const int smem_bytes = 2 * BUF_WORDS * 4;   // 86784

    cudaFuncSetAttribute(conv_tc<8, false>,
                         cudaFuncAttributeMaxDynamicSharedMemorySize, smem_bytes);
    cudaFuncSetAttribute(conv_tc<16, true>,
                         cudaFuncAttributeMaxDynamicSharedMemorySize, smem_bytes);

    unsigned* w1p; cudaGetSymbolAddress((void**)&w1p, g_W1p);
    unsigned* w2p; cudaGetSymbolAddress((void**)&w2p, g_W2p);
    unsigned* wrp; cudaGetSymbolAddress((void**)&wrp, g_Wrp);
    float* xtf;    cudaGetSymbolAddress((void**)&xtf, g_xtf);
    float* h1;     cudaGetSymbolAddress((void**)&h1, g_h1);

    prep_x_kernel<<<(kB * kCIN * kH * kW) / (256 * 4), 256>>>(x);
    prep_w_all<<<2048, 256>>>(W1, W2, Wr);
    router_kernel<<<kB * kHp * kWp, 128>>>(x, Rw1, Rb1, Rw2, Rb2);

    dim3 grid(kW / 32, kH / 4, kB);  // (4, 32, 8) = 1024 CTAs
    for (int e = 0; e < kE; e++) {
        conv_tc<8, false><<<grid, CTA_THREADS, smem_bytes>>>(
            xtf, w1p + (size_t)e * kCIN * 9 * 128, nullptr,
            b1 + e * kCOUT, nullptr, e, 0, nullptr);
        conv_tc<16, true><<<grid, CTA_THREADS, smem_bytes>>>(
            h1, w2p + (size_t)e * kCOUT * 9 * 128, wrp + (size_t)e * 8192,
            b2 + e * kCOUT, br + e * kCOUT, e, (e == 0) ? 1 : 0, out);
    }

    gn_partial_kernel<<<kB * kG * 32, 256>>>(out);
    gn_final_kernel<<<kB * kG, 32>>>();
    gn_apply_kernel<<<(kB * kCOUT * kH * kW) / (256 * 4), 256>>>(out, gamma, beta);
}

// round 15
// speedup vs baseline: 1.0516x; 1.0516x over previous
#include <cuda_runtime.h>

// ---------------------------------------------------------------------------
// PCELayer R15: R12 conv kernels, merged scheduling.
//  - conv1_all: one launch over (expert, batch) = grid.z 64 -> 2% wave tail
//  - conv2_all: one launch; per-CTA flat 192-chunk pipeline over all 8 experts
//    (continuous double-buffering across expert boundaries, private out RMW)
// ---------------------------------------------------------------------------

#define kB    8
#define kCIN  64
#define kCOUT 128
#define kH    128
#define kW    128
#define kE    8
#define kHp   8
#define kWp   8
#define kHID  128
#define kGCH  80
#define kG    8

// scratch (g_h1 now per-expert: 8 * 67 MB)
__device__ float    g_h1[kE * kB * kCOUT * kH * kW];
__device__ float    g_xtf[kB * kCIN * kH * kW];
__device__ unsigned g_W1p[kE * kCIN * 9 * 128];
__device__ unsigned g_W2p[kE * kCOUT * 9 * 128];
__device__ unsigned g_Wrp[kE * (kCIN / 8) * 1024];
__device__ float    g_gates[kB * kHp * kWp * kE];
__device__ double   g_part[kB * kG * 32 * 2];
__device__ float    g_stats[kB * kG * 2];

// ---------------------------------------------------------------------------
// helpers
// ---------------------------------------------------------------------------
__device__ __forceinline__ unsigned f2tf(float f) {
    unsigned u;
    asm("cvt.rna.tf32.f32 %0, %1;" : "=r"(u) : "f"(f));
    return u;
}

__device__ __forceinline__ void mma_tf32(float acc[4], unsigned a0, unsigned a1,
                                         unsigned a2, unsigned a3,
                                         unsigned b0, unsigned b1) {
    asm volatile(
        "mma.sync.aligned.m16n8k8.row.col.f32.tf32.tf32.f32 "
        "{%0,%1,%2,%3}, {%4,%5,%6,%7}, {%8,%9}, {%0,%1,%2,%3};\n"
        : "+f"(acc[0]), "+f"(acc[1]), "+f"(acc[2]), "+f"(acc[3])
        : "r"(a0), "r"(a1), "r"(a2), "r"(a3), "r"(b0), "r"(b1));
}

__device__ __forceinline__ void cp_async16(unsigned* dst, const void* src) {
    unsigned d = (unsigned)__cvta_generic_to_shared(dst);
    asm volatile("cp.async.cg.shared.global [%0], [%1], 16;" :: "r"(d), "l"(src));
}
__device__ __forceinline__ void cp_async4z(unsigned* dst, const void* src, bool ok) {
    unsigned d = (unsigned)__cvta_generic_to_shared(dst);
    int sz = ok ? 4 : 0;
    asm volatile("cp.async.ca.shared.global [%0], [%1], 4, %2;" :: "r"(d), "l"(src), "r"(sz));
}
__device__ __forceinline__ void cp_commit() {
    asm volatile("cp.async.commit_group;");
}
template <int N>
__device__ __forceinline__ void cp_wait() {
    asm volatile("cp.async.wait_group %0;" :: "n"(N));
}

// ---------------------------------------------------------------------------
// Prep (unchanged layouts)
// ---------------------------------------------------------------------------
__global__ void prep_x_kernel(const float* __restrict__ x) {
    int idx = blockIdx.x * 256 + threadIdx.x;
    const float4* in = reinterpret_cast<const float4*>(x);
    float4 v = in[idx];
    float4 o;
    o.x = __uint_as_float(f2tf(v.x));
    o.y = __uint_as_float(f2tf(v.y));
    o.z = __uint_as_float(f2tf(v.z));
    o.w = __uint_as_float(f2tf(v.w));
    reinterpret_cast<float4*>(g_xtf)[idx] = o;
}

__device__ __forceinline__ unsigned perm_w3x3(const float* W, int CIN, int idx) {
    int perE = CIN * 1152;
    int e = idx / perE;
    int r = idx - e * perE;
    int chunk = r / 9216;
    int r2 = r - chunk * 9216;
    int tap = r2 >> 10;
    int r3 = r2 & 1023;
    int ct = r3 >> 7;
    int lane = (r3 >> 2) & 31;
    int j = r3 & 3;
    int co = ct * 16 + (lane >> 2) + (j & 1) * 8;
    int ci = chunk * 8 + (lane & 3) + (j >> 1) * 4;
    return f2tf(W[((size_t)(e * 128 + co) * CIN + ci) * 9 + tap]);
}

__global__ void prep_w_all(const float* __restrict__ W1,
                           const float* __restrict__ W2,
                           const float* __restrict__ Wr)
{
    const int N1 = kE * kCIN  * 9 * 128;
    const int N2 = kE * kCOUT * 9 * 128;
    const int N3 = kE * 8192;
    for (int idx = blockIdx.x * 256 + threadIdx.x; idx < N1 + N2 + N3;
         idx += gridDim.x * 256) {
        if (idx < N1) {
            g_W1p[idx] = perm_w3x3(W1, kCIN, idx);
        } else if (idx < N1 + N2) {
            int i2 = idx - N1;
            g_W2p[i2] = perm_w3x3(W2, kCOUT, i2);
        } else {
            int i3 = idx - N1 - N2;
            int e = i3 >> 13;
            int r = i3 & 8191;
            int chunk = r >> 10;
            int r3 = r & 1023;
            int ct = r3 >> 7;
            int lane = (r3 >> 2) & 31;
            int j = r3 & 3;
            int co = ct * 16 + (lane >> 2) + (j & 1) * 8;
            int ci = chunk * 8 + (lane & 3) + (j >> 1) * 4;
            g_Wrp[i3] = f2tf(Wr[(e * 128 + co) * kCIN + ci]);
        }
    }
}

// ---------------------------------------------------------------------------
// Router (unchanged)
// ---------------------------------------------------------------------------
__global__ void router_kernel(const float* __restrict__ x,
                              const float* __restrict__ Rw1,
                              const float* __restrict__ Rb1,
                              const float* __restrict__ Rw2,
                              const float* __restrict__ Rb2)
{
    __shared__ float s_g[kGCH];
    __shared__ float s_h[kHID];
    __shared__ float s_l[kE];

    const int blk = blockIdx.x;
    const int b  = blk >> 6;
    const int hp = (blk >> 3) & 7;
    const int wp = blk & 7;
    const int t  = threadIdx.x;

    if (t < 64) {
        const float* xp = x + ((b * kCIN + t) * kH + hp * 16) * kW + wp * 16;
        float s = 0.f;
        for (int r = 0; r < 16; r++) {
            const float4* rp = reinterpret_cast<const float4*>(xp + r * kW);
            #pragma unroll
            for (int c4 = 0; c4 < 4; c4++) {
                float4 v = rp[c4];
                s += v.x + v.y + v.z + v.w;
            }
        }
        s_g[t] = s * (1.f / 256.f);
    } else if (t < 80) {
        int k = t - 64;
        int f = k & 3;
        int kind = k >> 2;
        float freq = (float)(1 << f) * 3.14159265358979323846f;
        float coord = (kind < 2) ? ((hp + 0.5f) / 8.0f) : ((wp + 0.5f) / 8.0f);
        float a = coord * freq;
        s_g[t] = (kind & 1) ? cosf(a) : sinf(a);
    }
    __syncthreads();

    {
        float hsum = Rb1[t];
        #pragma unroll 4
        for (int c = 0; c < kGCH; c++) hsum = fmaf(s_g[c], Rw1[c * kHID + t], hsum);
        s_h[t] = fmaxf(hsum, 0.f);
    }
    __syncthreads();

    if (t < kE) {
        float l = Rb2[t];
        #pragma unroll 4
        for (int d = 0; d < kHID; d++) l = fmaf(s_h[d], Rw2[d * kE + t], l);
        s_l[t] = l;
    }
    __syncthreads();

    if (t == 0) {
        float m = s_l[0];
        #pragma unroll
        for (int e = 1; e < kE; e++) m = fmaxf(m, s_l[e]);
        float ex[kE];
        float ssum = 0.f;
        #pragma unroll
        for (int e = 0; e < kE; e++) { ex[e] = expf(s_l[e] - m); ssum += ex[e]; }
        float inv = 1.f / ssum;
        #pragma unroll
        for (int e = 0; e < kE; e++)
            g_gates[((b * kHp + hp) * kWp + wp) * kE + e] = ex[e] * inv;
    }
}

// ---------------------------------------------------------------------------
// Conv tiling (R12): CTA 128co x (32x x 4y), 256 thr, 8 warps:
// wm = w>>2 (64 co), wy = w&3 (1 row). Per tap: 4 LDS.128 A + 4 LDS.64 B.
// Input smem: uint2 planes [cp=ci&3][row 6][col 34], plane stride 204 uint2.
// ---------------------------------------------------------------------------
#define W_WORDS   9216
#define IN_WORDS  1632
#define BUF_WORDS (W_WORDS + IN_WORDS)   // 10848 words = 43392 B

// shared staging: src base + layout identical for both kernels
__device__ __forceinline__ void stage_job(unsigned* dyn, int bufi,
                                          const float* __restrict__ src,
                                          int plane0,   // (plane index) * kH*kW base rows
                                          const unsigned* __restrict__ wsrc, int wn,
                                          int gy0, int gx0, int t)
{
    unsigned* bw  = dyn + bufi * BUF_WORDS;
    unsigned* bin = bw + W_WORDS;
    for (int i = t; i < wn / 4; i += 256)
        cp_async16(bw + i * 4, wsrc + i * 4);
    for (int idx = t; idx < 8 * 6 * 34; idx += 256) {
        int ci  = idx / 204;
        int rem = idx - ci * 204;
        int row = rem / 34;
        int col = rem - row * 34;
        int gy = gy0 + row - 1;
        int gx = gx0 + col - 1;
        bool ok = ((unsigned)gy < (unsigned)kH) && ((unsigned)gx < (unsigned)kW);
        const float* sp = ok
            ? src + ((size_t)(plane0 + ci) * kH + gy) * kW + gx
            : src;
        cp_async4z(bin + (ci & 3) * 408 + rem * 2 + (ci >> 2), sp, ok);
    }
    cp_commit();
}

__device__ __forceinline__ void mma_main(unsigned* dyn, int bufi, int wm, int wy,
                                         int g, int tin, int lane, float acc[4][4][4])
{
    unsigned* bw = dyn + bufi * BUF_WORDS;
    const uint4* aw = reinterpret_cast<const uint4*>(bw);
    const uint2* sinp = reinterpret_cast<const uint2*>(bw + W_WORDS);
    #pragma unroll
    for (int tap = 0; tap < 9; tap++) {
        const int dy = tap / 3, dx = tap % 3;
        uint4 A[4];
        #pragma unroll
        for (int mt = 0; mt < 4; mt++)
            A[mt] = aw[(tap * 8 + wm * 4 + mt) * 32 + lane];
        const int row = wy + dy;
        const uint2* rp = sinp + tin * 204 + row * 34 + dx + g;
        #pragma unroll
        for (int nt = 0; nt < 4; nt++) {
            uint2 b01 = rp[nt * 8];
            #pragma unroll
            for (int mt = 0; mt < 4; mt++)
                mma_tf32(acc[mt][nt], A[mt].x, A[mt].y, A[mt].z, A[mt].w,
                         b01.x, b01.y);
        }
    }
}

__device__ __forceinline__ void mma_res(unsigned* dyn, int bufi, int wm, int wy,
                                        int g, int tin, int lane, float acc[4][4][4])
{
    unsigned* bw = dyn + bufi * BUF_WORDS;
    const uint4* aw = reinterpret_cast<const uint4*>(bw);
    const uint2* sinp = reinterpret_cast<const uint2*>(bw + W_WORDS);
    uint4 A[4];
    #pragma unroll
    for (int mt = 0; mt < 4; mt++)
        A[mt] = aw[(wm * 4 + mt) * 32 + lane];
    const int row = wy + 1;
    const uint2* rp = sinp + tin * 204 + row * 34 + 1 + g;
    #pragma unroll
    for (int nt = 0; nt < 4; nt++) {
        uint2 b01 = rp[nt * 8];
        #pragma unroll
        for (int mt = 0; mt < 4; mt++)
            mma_tf32(acc[mt][nt], A[mt].x, A[mt].y, A[mt].z, A[mt].w,
                     b01.x, b01.y);
    }
}

// ---------------------------------------------------------------------------
// conv1_all: all experts in one launch. grid (4, 32, 64), z = e*8 + b.
// ---------------------------------------------------------------------------
__global__ void __launch_bounds__(256)
conv1_all(const unsigned* __restrict__ w1p, const float* __restrict__ b1)
{
    extern __shared__ unsigned dyn[];
    const int t = threadIdx.x;
    const int lane = t & 31, w = t >> 5;
    const int g = lane >> 2, tin = lane & 3;
    const int wm = w >> 2, wy = w & 3;
    const int gx0 = blockIdx.x * 32, gy0 = blockIdx.y * 4;
    const int e = blockIdx.z >> 3, b = blockIdx.z & 7;

    const unsigned* wbase = w1p + (size_t)e * 8 * W_WORDS;

    float acc[4][4][4];
    #pragma unroll
    for (int mt = 0; mt < 4; mt++)
        #pragma unroll
        for (int nt = 0; nt < 4; nt++)
            #pragma unroll
            for (int u = 0; u < 4; u++) acc[mt][nt][u] = 0.f;

    stage_job(dyn, 0, g_xtf, b * kCIN, wbase, W_WORDS, gy0, gx0, t);
    for (int j = 0; j < 8; j++) {
        if (j + 1 < 8) {
            stage_job(dyn, (j + 1) & 1, g_xtf, b * kCIN + (j + 1) * 8,
                      wbase + (j + 1) * W_WORDS, W_WORDS, gy0, gx0, t);
            cp_wait<1>();
        } else {
            cp_wait<0>();
        }
        __syncthreads();
        mma_main(dyn, j & 1, wm, wy, g, tin, lane, acc);
        __syncthreads();
    }

    const int y = gy0 + wy;
    const float* bias = b1 + e * kCOUT;
    #pragma unroll
    for (int mt = 0; mt < 4; mt++) {
        int co0 = wm * 64 + mt * 16 + g;
        float bb0 = bias[co0], bb1 = bias[co0 + 8];
        #pragma unroll
        for (int nt = 0; nt < 4; nt++) {
            int gx = gx0 + nt * 8 + tin * 2;
            float2 o0, o1;
            o0.x = __uint_as_float(f2tf(fmaxf(acc[mt][nt][0] + bb0, 0.f)));
            o0.y = __uint_as_float(f2tf(fmaxf(acc[mt][nt][1] + bb0, 0.f)));
            o1.x = __uint_as_float(f2tf(fmaxf(acc[mt][nt][2] + bb1, 0.f)));
            o1.y = __uint_as_float(f2tf(fmaxf(acc[mt][nt][3] + bb1, 0.f)));
            *reinterpret_cast<float2*>(
                &g_h1[(((size_t)(e * kB + b) * kCOUT + co0    ) * kH + y) * kW + gx]) = o0;
            *reinterpret_cast<float2*>(
                &g_h1[(((size_t)(e * kB + b) * kCOUT + co0 + 8) * kH + y) * kW + gx]) = o1;
        }
    }
}

// ---------------------------------------------------------------------------
// conv2_all: one launch; per-CTA flat pipeline over 8 experts x 24 jobs.
// grid (4, 32, 8), z = b.  Private out-tile RMW per expert (tile-exclusive).
// ---------------------------------------------------------------------------
__global__ void __launch_bounds__(256)
conv2_all(const unsigned* __restrict__ w2p, const unsigned* __restrict__ wrp,
          const float* __restrict__ b2, const float* __restrict__ br,
          float* __restrict__ out)
{
    extern __shared__ unsigned dyn[];
    const int t = threadIdx.x;
    const int lane = t & 31, w = t >> 5;
    const int g = lane >> 2, tin = lane & 3;
    const int wm = w >> 2, wy = w & 3;
    const int gx0 = blockIdx.x * 32, gy0 = blockIdx.y * 4;
    const int b = blockIdx.z;

    auto issue = [&](int J) {
        int e2 = J / 24;
        int j2 = J - e2 * 24;
        if (j2 < 16) {
            stage_job(dyn, J & 1, g_h1, (e2 * kB + b) * kCOUT + j2 * 8,
                      w2p + ((size_t)e2 * 16 + j2) * W_WORDS, W_WORDS, gy0, gx0, t);
        } else {
            int jr = j2 - 16;
            stage_job(dyn, J & 1, g_xtf, b * kCIN + jr * 8,
                      wrp + (size_t)e2 * 8192 + jr * 1024, 1024, gy0, gx0, t);
        }
    };

    float acc[4][4][4];
    #pragma unroll
    for (int mt = 0; mt < 4; mt++)
        #pragma unroll
        for (int nt = 0; nt < 4; nt++)
            #pragma unroll
            for (int u = 0; u < 4; u++) acc[mt][nt][u] = 0.f;

    issue(0);
    for (int J = 0; J < kE * 24; J++) {
        const int e = J / 24;
        const int j = J - e * 24;
        if (J + 1 < kE * 24) {
            issue(J + 1);
            cp_wait<1>();
        } else {
            cp_wait<0>();
        }
        __syncthreads();
        if (j < 16) mma_main(dyn, J & 1, wm, wy, g, tin, lane, acc);
        else        mma_res (dyn, J & 1, wm, wy, g, tin, lane, acc);
        __syncthreads();

        if (j == 23) {
            // epilogue for expert e: gated RMW into private out tile
            const int y = gy0 + wy;
            const int prow = (b * kHp + (y >> 4)) * kWp;
            const float gateL = g_gates[(prow + ((gx0      ) >> 4)) * kE + e];
            const float gateR = g_gates[(prow + ((gx0 + 16) >> 4)) * kE + e];
            #pragma unroll
            for (int mt = 0; mt < 4; mt++) {
                int co0 = wm * 64 + mt * 16 + g;
                float bb0 = b2[e * kCOUT + co0] + br[e * kCOUT + co0];
                float bb1 = b2[e * kCOUT + co0 + 8] + br[e * kCOUT + co0 + 8];
                #pragma unroll
                for (int nt = 0; nt < 4; nt++) {
                    const float gate = (nt < 2) ? gateL : gateR;
                    int gx = gx0 + nt * 8 + tin * 2;
                    float2 o0, o1;
                    o0.x = fmaxf(acc[mt][nt][0] + bb0, 0.f) * gate;
                    o0.y = fmaxf(acc[mt][nt][1] + bb0, 0.f) * gate;
                    o1.x = fmaxf(acc[mt][nt][2] + bb1, 0.f) * gate;
                    o1.y = fmaxf(acc[mt][nt][3] + bb1, 0.f) * gate;
                    float2* p0 = reinterpret_cast<float2*>(
                        &out[((b * kCOUT + co0    ) * kH + y) * kW + gx]);
                    float2* p1 = reinterpret_cast<float2*>(
                        &out[((b * kCOUT + co0 + 8) * kH + y) * kW + gx]);
                    if (e != 0) {
                        float2 v0 = *p0, v1 = *p1;
                        o0.x += v0.x; o0.y += v0.y;
                        o1.x += v1.x; o1.y += v1.y;
                    }
                    *p0 = o0;
                    *p1 = o1;
                    // reset acc for next expert
                    acc[mt][nt][0] = 0.f; acc[mt][nt][1] = 0.f;
                    acc[mt][nt][2] = 0.f; acc[mt][nt][3] = 0.f;
                }
            }
        }
    }
}

// ---------------------------------------------------------------------------
// GroupNorm (unchanged)
// ---------------------------------------------------------------------------
__global__ void gn_partial_kernel(const float* __restrict__ y)
{
    const int bid = blockIdx.x;
    const int bg = bid >> 5, sl = bid & 31;
    const int t = threadIdx.x;
    const float4* p = reinterpret_cast<const float4*>(
        y + (size_t)bg * ((kCOUT / kG) * kH * kW) + sl * 8192);

    double s = 0.0, q = 0.0;
    for (int i = t; i < 2048; i += 256) {
        float4 v = p[i];
        s += (double)v.x + (double)v.y + (double)v.z + (double)v.w;
        q += (double)v.x * v.x + (double)v.y * v.y +
             (double)v.z * v.z + (double)v.w * v.w;
    }
    __shared__ double sh_s[256], sh_q[256];
    sh_s[t] = s; sh_q[t] = q;
    __syncthreads();
    for (int off = 128; off > 0; off >>= 1) {
        if (t < off) { sh_s[t] += sh_s[t + off]; sh_q[t] += sh_q[t + off]; }
        __syncthreads();
    }
    if (t == 0) {
        g_part[(bg * 32 + sl) * 2 + 0] = sh_s[0];
        g_part[(bg * 32 + sl) * 2 + 1] = sh_q[0];
    }
}

__global__ void gn_final_kernel()
{
    const int bg = blockIdx.x;
    const int t = threadIdx.x;
    double s = g_part[(bg * 32 + t) * 2 + 0];
    double q = g_part[(bg * 32 + t) * 2 + 1];
    #pragma unroll
    for (int off = 16; off > 0; off >>= 1) {
        s += __shfl_down_sync(0xffffffffu, s, off);
        q += __shfl_down_sync(0xffffffffu, q, off);
    }
    if (t == 0) {
        const double N = (double)((kCOUT / kG) * kH * kW);
        double mean = s / N;
        double var  = q / N - mean * mean;
        g_stats[bg * 2 + 0] = (float)mean;
        g_stats[bg * 2 + 1] = (float)(1.0 / sqrt(var + 1e-5));
    }
}

__global__ void gn_apply_kernel(float* __restrict__ y,
                                const float* __restrict__ gamma,
                                const float* __restrict__ beta)
{
    const int idx4 = blockIdx.x * 256 + threadIdx.x;
    const int idx = idx4 * 4;
    const int c = (idx >> 14) & 127;
    const int bg = idx >> 18;
    const float mean = g_stats[bg * 2 + 0];
    const float rstd = g_stats[bg * 2 + 1];
    const float ga = gamma[c] * rstd;
    const float be = beta[c] - mean * ga;
    float4 v = *reinterpret_cast<float4*>(&y[idx]);
    v.x = v.x * ga + be;
    v.y = v.y * ga + be;
    v.z = v.z * ga + be;
    v.w = v.w * ga + be;
    *reinterpret_cast<float4*>(&y[idx]) = v;
}

// ---------------------------------------------------------------------------
// Launch
// ---------------------------------------------------------------------------
extern "C" void kernel_launch(void* const* d_in, const int* in_sizes, int n_in,
                              void* d_out, int out_size)
{
    const float* x     = (const float*)d_in[0];
    const float* W1    = (const float*)d_in[1];
    const float* b1    = (const float*)d_in[2];
    const float* W2    = (const float*)d_in[3];
    const float* b2    = (const float*)d_in[4];
    const float* Wr    = (const float*)d_in[5];
    const float* br    = (const float*)d_in[6];
    const float* Rw1   = (const float*)d_in[7];
    const float* Rb1   = (const float*)d_in[8];
    const float* Rw2   = (const float*)d_in[9];
    const float* Rb2   = (const float*)d_in[10];
    const float* gamma = (const float*)d_in[11];
    const float* beta  = (const float*)d_in[12];
    float* out = (float*)d_out;

    const int smem_bytes = 2 * BUF_WORDS * 4;   // 86784

    cudaFuncSetAttribute(conv1_all,
                         cudaFuncAttributeMaxDynamicSharedMemorySize, smem_bytes);
    cudaFuncSetAttribute(conv2_all,
                         cudaFuncAttributeMaxDynamicSharedMemorySize, smem_bytes);

    unsigned* w1p; cudaGetSymbolAddress((void**)&w1p, g_W1p);
    unsigned* w2p; cudaGetSymbolAddress((void**)&w2p, g_W2p);
    unsigned* wrp; cudaGetSymbolAddress((void**)&wrp, g_Wrp);

    prep_x_kernel<<<(kB * kCIN * kH * kW) / (256 * 4), 256>>>(x);
    prep_w_all<<<2048, 256>>>(W1, W2, Wr);
    router_kernel<<<kB * kHp * kWp, 128>>>(x, Rw1, Rb1, Rw2, Rb2);

    conv1_all<<<dim3(4, 32, 64), 256, smem_bytes>>>(w1p, b1);
    conv2_all<<<dim3(4, 32, 8), 256, smem_bytes>>>(w2p, wrp, b2, br, out);

    gn_partial_kernel<<<kB * kG * 32, 256>>>(out);
    gn_final_kernel<<<kB * kG, 32>>>();
    gn_apply_kernel<<<(kB * kCOUT * kH * kW) / (256 * 4), 256>>>(out, gamma, beta);
}

// round 16
// speedup vs baseline: 1.9609x; 1.8646x over previous
#include <cuda_runtime.h>
#include <cuda_fp16.h>

// ---------------------------------------------------------------------------
// PCELayer R16: fp16 mma.sync.m16n8k16 (same 10-bit mantissa as tf32, 2x MACs
// per instruction).  R15 merged schedule + R12 tiling.
//  - x / h1 / weights in f16, k-paired (ch j, ch j+8) per 16-ci chunk
//  - conv1 epilogue writes h1 directly in packed pair-plane layout
// ---------------------------------------------------------------------------

#define kB    8
#define kCIN  64
#define kCOUT 128
#define kH    128
#define kW    128
#define kE    8
#define kHp   8
#define kWp   8
#define kHID  128
#define kGCH  80
#define kG    8

// scratch
__device__ unsigned g_xh [kB * 4 * 8 * kH * kW];          // x f16x2 pair-planes
__device__ unsigned g_h1h[kE * kB * 8 * 8 * kH * kW];     // h1 f16x2 pair-planes
__device__ unsigned g_W1h[kE * 4 * 9216];                 // A images (f16x2)
__device__ unsigned g_W2h[kE * 8 * 9216];
__device__ unsigned g_Wrh[kE * 4 * 1024];
__device__ float    g_gates[kB * kHp * kWp * kE];
__device__ double   g_part[kB * kG * 32 * 2];
__device__ float    g_stats[kB * kG * 2];

// ---------------------------------------------------------------------------
// helpers
// ---------------------------------------------------------------------------
__device__ __forceinline__ unsigned packh2(float lo, float hi) {
    __half2 h = __halves2half2(__float2half_rn(lo), __float2half_rn(hi));
    return *reinterpret_cast<unsigned*>(&h);
}

__device__ __forceinline__ void mma_f16(float acc[4], unsigned a0, unsigned a1,
                                        unsigned a2, unsigned a3,
                                        unsigned b0, unsigned b1) {
    asm volatile(
        "mma.sync.aligned.m16n8k16.row.col.f32.f16.f16.f32 "
        "{%0,%1,%2,%3}, {%4,%5,%6,%7}, {%8,%9}, {%0,%1,%2,%3};\n"
        : "+f"(acc[0]), "+f"(acc[1]), "+f"(acc[2]), "+f"(acc[3])
        : "r"(a0), "r"(a1), "r"(a2), "r"(a3), "r"(b0), "r"(b1));
}

__device__ __forceinline__ void cp_async16(unsigned* dst, const void* src) {
    unsigned d = (unsigned)__cvta_generic_to_shared(dst);
    asm volatile("cp.async.cg.shared.global [%0], [%1], 16;" :: "r"(d), "l"(src));
}
__device__ __forceinline__ void cp_async4z(unsigned* dst, const void* src, bool ok) {
    unsigned d = (unsigned)__cvta_generic_to_shared(dst);
    int sz = ok ? 4 : 0;
    asm volatile("cp.async.ca.shared.global [%0], [%1], 4, %2;" :: "r"(d), "l"(src), "r"(sz));
}
__device__ __forceinline__ void cp_commit() {
    asm volatile("cp.async.commit_group;");
}
template <int N>
__device__ __forceinline__ void cp_wait() {
    asm volatile("cp.async.wait_group %0;" :: "n"(N));
}

// ---------------------------------------------------------------------------
// Prep.
// x pair-planes: g_xh[((b*4+chunk)*8+slot)*16384 + pix], slot s -> pair
//   m = (s>>1) + (s&1)*4, word = f16x2(x[ch m], x[ch m+8]) (ch rel chunk*16).
// A image per (chunk, tap): [mtile 8][lane 32][j 4]:
//   row = mt*16 + (lane>>2) + (j&1)*8 ; pair = (lane&3) + (j>>1)*4
//   word = f16x2(W[row][chunk*16+pair], W[row][chunk*16+pair+8])
// ---------------------------------------------------------------------------
__global__ void prep_x_kernel(const float* __restrict__ x) {
    int idx = blockIdx.x * 256 + threadIdx.x;   // word index
    int b = idx >> 19;
    int r = idx & 524287;
    int chunk = r >> 17;
    int r2 = r & 131071;
    int slot = r2 >> 14;
    int pix = r2 & 16383;
    int m = (slot >> 1) + (slot & 1) * 4;
    int ch0 = chunk * 16 + m;
    g_xh[idx] = packh2(x[(b * kCIN + ch0) * 16384 + pix],
                       x[(b * kCIN + ch0 + 8) * 16384 + pix]);
}

__device__ __forceinline__ unsigned perm_w3x3(const float* W, int CIN, int e, int r) {
    int chunk = r / 9216;
    int r2 = r - chunk * 9216;
    int tap = r2 >> 10;
    int r3 = r2 & 1023;
    int mt = r3 >> 7;
    int lane = (r3 >> 2) & 31;
    int j = r3 & 3;
    int row = mt * 16 + (lane >> 2) + (j & 1) * 8;
    int pair = (lane & 3) + ((j >> 1) << 2);
    int ci0 = chunk * 16 + pair;
    const float* wp = W + ((size_t)(e * 128 + row) * CIN) * 9 + tap;
    return packh2(wp[ci0 * 9], wp[(ci0 + 8) * 9]);
}

__global__ void prep_w_all(const float* __restrict__ W1,
                           const float* __restrict__ W2,
                           const float* __restrict__ Wr)
{
    const int N1 = kE * 4 * 9216;    // 294912
    const int N2 = kE * 8 * 9216;    // 589824
    const int N3 = kE * 4 * 1024;    // 32768
    for (int idx = blockIdx.x * 256 + threadIdx.x; idx < N1 + N2 + N3;
         idx += gridDim.x * 256) {
        if (idx < N1) {
            int e = idx / 36864;
            g_W1h[idx] = perm_w3x3(W1, kCIN, e, idx - e * 36864);
        } else if (idx < N1 + N2) {
            int i2 = idx - N1;
            int e = i2 / 73728;
            g_W2h[i2] = perm_w3x3(W2, kCOUT, e, i2 - e * 73728);
        } else {
            int i3 = idx - N1 - N2;
            int e = i3 >> 12;
            int r = i3 & 4095;
            int chunk = r >> 10;
            int r3 = r & 1023;
            int mt = r3 >> 7;
            int lane = (r3 >> 2) & 31;
            int j = r3 & 3;
            int row = mt * 16 + (lane >> 2) + (j & 1) * 8;
            int pair = (lane & 3) + ((j >> 1) << 2);
            int ci0 = chunk * 16 + pair;
            g_Wrh[i3] = packh2(Wr[(e * 128 + row) * kCIN + ci0],
                               Wr[(e * 128 + row) * kCIN + ci0 + 8]);
        }
    }
}

// ---------------------------------------------------------------------------
// Router (unchanged, reads fp32 x)
// ---------------------------------------------------------------------------
__global__ void router_kernel(const float* __restrict__ x,
                              const float* __restrict__ Rw1,
                              const float* __restrict__ Rb1,
                              const float* __restrict__ Rw2,
                              const float* __restrict__ Rb2)
{
    __shared__ float s_g[kGCH];
    __shared__ float s_h[kHID];
    __shared__ float s_l[kE];

    const int blk = blockIdx.x;
    const int b  = blk >> 6;
    const int hp = (blk >> 3) & 7;
    const int wp = blk & 7;
    const int t  = threadIdx.x;

    if (t < 64) {
        const float* xp = x + ((b * kCIN + t) * kH + hp * 16) * kW + wp * 16;
        float s = 0.f;
        for (int r = 0; r < 16; r++) {
            const float4* rp = reinterpret_cast<const float4*>(xp + r * kW);
            #pragma unroll
            for (int c4 = 0; c4 < 4; c4++) {
                float4 v = rp[c4];
                s += v.x + v.y + v.z + v.w;
            }
        }
        s_g[t] = s * (1.f / 256.f);
    } else if (t < 80) {
        int k = t - 64;
        int f = k & 3;
        int kind = k >> 2;
        float freq = (float)(1 << f) * 3.14159265358979323846f;
        float coord = (kind < 2) ? ((hp + 0.5f) / 8.0f) : ((wp + 0.5f) / 8.0f);
        float a = coord * freq;
        s_g[t] = (kind & 1) ? cosf(a) : sinf(a);
    }
    __syncthreads();

    {
        float hsum = Rb1[t];
        #pragma unroll 4
        for (int c = 0; c < kGCH; c++) hsum = fmaf(s_g[c], Rw1[c * kHID + t], hsum);
        s_h[t] = fmaxf(hsum, 0.f);
    }
    __syncthreads();

    if (t < kE) {
        float l = Rb2[t];
        #pragma unroll 4
        for (int d = 0; d < kHID; d++) l = fmaf(s_h[d], Rw2[d * kE + t], l);
        s_l[t] = l;
    }
    __syncthreads();

    if (t == 0) {
        float m = s_l[0];
        #pragma unroll
        for (int e = 1; e < kE; e++) m = fmaxf(m, s_l[e]);
        float ex[kE];
        float ssum = 0.f;
        #pragma unroll
        for (int e = 0; e < kE; e++) { ex[e] = expf(s_l[e] - m); ssum += ex[e]; }
        float inv = 1.f / ssum;
        #pragma unroll
        for (int e = 0; e < kE; e++)
            g_gates[((b * kHp + hp) * kWp + wp) * kE + e] = ex[e] * inv;
    }
}

// ---------------------------------------------------------------------------
// Conv tiling: CTA 128co x (32x x 4y), 256 thr, 8 warps: wm=w>>2, wy=w&3.
// Per tap: 4 LDS.128 A + 4 LDS.64 B -> 16 MMA (k16).
// In-tile smem: pixel-major, 8 f16x2 words per pixel (slots), rows 6, cols 34.
// ---------------------------------------------------------------------------
#define W_WORDS   9216
#define IN_WORDS  1632              // 6*34 px * 8 slots
#define BUF_WORDS (W_WORDS + IN_WORDS)   // 10848 words = 43392 B

__device__ __forceinline__ void stage_job(unsigned* dyn, int bufi,
                                          const unsigned* __restrict__ srcw,
                                          int plane0,
                                          const unsigned* __restrict__ wsrc, int wn,
                                          int gy0, int gx0, int t)
{
    unsigned* bw  = dyn + bufi * BUF_WORDS;
    unsigned* bin = bw + W_WORDS;
    for (int i = t; i < wn / 4; i += 256)
        cp_async16(bw + i * 4, wsrc + i * 4);
    for (int idx = t; idx < IN_WORDS; idx += 256) {
        int pp  = idx / 204;
        int rem = idx - pp * 204;
        int row = rem / 34;
        int col = rem - row * 34;
        int gy = gy0 + row - 1;
        int gx = gx0 + col - 1;
        bool ok = ((unsigned)gy < (unsigned)kH) && ((unsigned)gx < (unsigned)kW);
        const unsigned* sp = srcw + (size_t)(plane0 + pp) * 16384
                           + (ok ? (gy * kW + gx) : 0);
        cp_async4z(bin + ((row * 34 + col) << 3) + pp, sp, ok);
    }
    cp_commit();
}

__device__ __forceinline__ void mma_main(unsigned* dyn, int bufi, int wm, int wy,
                                         int g, int tin, int lane, float acc[4][4][4])
{
    unsigned* bw = dyn + bufi * BUF_WORDS;
    const uint4* aw = reinterpret_cast<const uint4*>(bw);
    const uint2* sinp = reinterpret_cast<const uint2*>(bw + W_WORDS);
    #pragma unroll
    for (int tap = 0; tap < 9; tap++) {
        const int dy = tap / 3, dx = tap % 3;
        uint4 A[4];
        #pragma unroll
        for (int mt = 0; mt < 4; mt++)
            A[mt] = aw[(tap * 8 + wm * 4 + mt) * 32 + lane];
        const int row = wy + dy;
        const uint2* rp = sinp + (row * 34 + dx + g) * 4 + tin;
        #pragma unroll
        for (int nt = 0; nt < 4; nt++) {
            uint2 b01 = rp[nt * 32];
            #pragma unroll
            for (int mt = 0; mt < 4; mt++)
                mma_f16(acc[mt][nt], A[mt].x, A[mt].y, A[mt].z, A[mt].w,
                        b01.x, b01.y);
        }
    }
}

__device__ __forceinline__ void mma_res(unsigned* dyn, int bufi, int wm, int wy,
                                        int g, int tin, int lane, float acc[4][4][4])
{
    unsigned* bw = dyn + bufi * BUF_WORDS;
    const uint4* aw = reinterpret_cast<const uint4*>(bw);
    const uint2* sinp = reinterpret_cast<const uint2*>(bw + W_WORDS);
    uint4 A[4];
    #pragma unroll
    for (int mt = 0; mt < 4; mt++)
        A[mt] = aw[(wm * 4 + mt) * 32 + lane];
    const int row = wy + 1;
    const uint2* rp = sinp + (row * 34 + 1 + g) * 4 + tin;
    #pragma unroll
    for (int nt = 0; nt < 4; nt++) {
        uint2 b01 = rp[nt * 32];
        #pragma unroll
        for (int mt = 0; mt < 4; mt++)
            mma_f16(acc[mt][nt], A[mt].x, A[mt].y, A[mt].z, A[mt].w,
                    b01.x, b01.y);
    }
}

// ---------------------------------------------------------------------------
// conv1_all: grid (4, 32, 64), z = e*8 + b.  4 jobs (16 ci each).
// Epilogue writes h1 in packed pair-plane f16 layout.
// ---------------------------------------------------------------------------
__global__ void __launch_bounds__(256)
conv1_all(const unsigned* __restrict__ w1h, const float* __restrict__ b1)
{
    extern __shared__ unsigned dyn[];
    const int t = threadIdx.x;
    const int lane = t & 31, w = t >> 5;
    const int g = lane >> 2, tin = lane & 3;
    const int wm = w >> 2, wy = w & 3;
    const int gx0 = blockIdx.x * 32, gy0 = blockIdx.y * 4;
    const int e = blockIdx.z >> 3, b = blockIdx.z & 7;

    const unsigned* wbase = w1h + (size_t)e * 4 * W_WORDS;

    float acc[4][4][4];
    #pragma unroll
    for (int mt = 0; mt < 4; mt++)
        #pragma unroll
        for (int nt = 0; nt < 4; nt++)
            #pragma unroll
            for (int u = 0; u < 4; u++) acc[mt][nt][u] = 0.f;

    stage_job(dyn, 0, g_xh, (b * 4 + 0) * 8, wbase, W_WORDS, gy0, gx0, t);
    for (int j = 0; j < 4; j++) {
        if (j + 1 < 4) {
            stage_job(dyn, (j + 1) & 1, g_xh, (b * 4 + j + 1) * 8,
                      wbase + (j + 1) * W_WORDS, W_WORDS, gy0, gx0, t);
            cp_wait<1>();
        } else {
            cp_wait<0>();
        }
        __syncthreads();
        mma_main(dyn, j & 1, wm, wy, g, tin, lane, acc);
        __syncthreads();
    }

    const int y = gy0 + wy;
    const float* bias = b1 + e * kCOUT;
    const int slot = (g < 4) ? (2 * g) : (2 * (g - 4) + 1);
    #pragma unroll
    for (int mt = 0; mt < 4; mt++) {
        int co0 = wm * 64 + mt * 16 + g;
        int chunkc = wm * 4 + mt;
        float bb0 = bias[co0], bb1 = bias[co0 + 8];
        size_t base = ((size_t)((e * kB + b) * 8 + chunkc) * 8 + slot) * 16384
                    + y * kW;
        #pragma unroll
        for (int nt = 0; nt < 4; nt++) {
            int gx = gx0 + nt * 8 + tin * 2;
            uint2 o;
            o.x = packh2(fmaxf(acc[mt][nt][0] + bb0, 0.f),
                         fmaxf(acc[mt][nt][2] + bb1, 0.f));
            o.y = packh2(fmaxf(acc[mt][nt][1] + bb0, 0.f),
                         fmaxf(acc[mt][nt][3] + bb1, 0.f));
            *reinterpret_cast<uint2*>(&g_h1h[base + gx]) = o;
        }
    }
}

// ---------------------------------------------------------------------------
// conv2_all: grid (4, 32, 8); flat 96-job pipeline (8 experts x (8 main + 4 res)).
// ---------------------------------------------------------------------------
__global__ void __launch_bounds__(256)
conv2_all(const unsigned* __restrict__ w2h, const unsigned* __restrict__ wrh,
          const float* __restrict__ b2, const float* __restrict__ br,
          float* __restrict__ out)
{
    extern __shared__ unsigned dyn[];
    const int t = threadIdx.x;
    const int lane = t & 31, w = t >> 5;
    const int g = lane >> 2, tin = lane & 3;
    const int wm = w >> 2, wy = w & 3;
    const int gx0 = blockIdx.x * 32, gy0 = blockIdx.y * 4;
    const int b = blockIdx.z;

    auto issue = [&](int J) {
        int e2 = J / 12;
        int j2 = J - e2 * 12;
        if (j2 < 8) {
            stage_job(dyn, J & 1, g_h1h, ((e2 * kB + b) * 8 + j2) * 8,
                      w2h + ((size_t)e2 * 8 + j2) * W_WORDS, W_WORDS, gy0, gx0, t);
        } else {
            int jr = j2 - 8;
            stage_job(dyn, J & 1, g_xh, (b * 4 + jr) * 8,
                      wrh + (size_t)e2 * 4096 + jr * 1024, 1024, gy0, gx0, t);
        }
    };

    float acc[4][4][4];
    #pragma unroll
    for (int mt = 0; mt < 4; mt++)
        #pragma unroll
        for (int nt = 0; nt < 4; nt++)
            #pragma unroll
            for (int u = 0; u < 4; u++) acc[mt][nt][u] = 0.f;

    issue(0);
    for (int J = 0; J < kE * 12; J++) {
        const int e = J / 12;
        const int j = J - e * 12;
        if (J + 1 < kE * 12) {
            issue(J + 1);
            cp_wait<1>();
        } else {
            cp_wait<0>();
        }
        __syncthreads();
        if (j < 8) mma_main(dyn, J & 1, wm, wy, g, tin, lane, acc);
        else       mma_res (dyn, J & 1, wm, wy, g, tin, lane, acc);
        __syncthreads();

        if (j == 11) {
            const int y = gy0 + wy;
            const int prow = (b * kHp + (y >> 4)) * kWp;
            const float gateL = g_gates[(prow + ((gx0      ) >> 4)) * kE + e];
            const float gateR = g_gates[(prow + ((gx0 + 16) >> 4)) * kE + e];
            #pragma unroll
            for (int mt = 0; mt < 4; mt++) {
                int co0 = wm * 64 + mt * 16 + g;
                float bb0 = b2[e * kCOUT + co0] + br[e * kCOUT + co0];
                float bb1 = b2[e * kCOUT + co0 + 8] + br[e * kCOUT + co0 + 8];
                #pragma unroll
                for (int nt = 0; nt < 4; nt++) {
                    const float gate = (nt < 2) ? gateL : gateR;
                    int gx = gx0 + nt * 8 + tin * 2;
                    float2 o0, o1;
                    o0.x = fmaxf(acc[mt][nt][0] + bb0, 0.f) * gate;
                    o0.y = fmaxf(acc[mt][nt][1] + bb0, 0.f) * gate;
                    o1.x = fmaxf(acc[mt][nt][2] + bb1, 0.f) * gate;
                    o1.y = fmaxf(acc[mt][nt][3] + bb1, 0.f) * gate;
                    float2* p0 = reinterpret_cast<float2*>(
                        &out[((b * kCOUT + co0    ) * kH + y) * kW + gx]);
                    float2* p1 = reinterpret_cast<float2*>(
                        &out[((b * kCOUT + co0 + 8) * kH + y) * kW + gx]);
                    if (e != 0) {
                        float2 v0 = *p0, v1 = *p1;
                        o0.x += v0.x; o0.y += v0.y;
                        o1.x += v1.x; o1.y += v1.y;
                    }
                    *p0 = o0;
                    *p1 = o1;
                    acc[mt][nt][0] = 0.f; acc[mt][nt][1] = 0.f;
                    acc[mt][nt][2] = 0.f; acc[mt][nt][3] = 0.f;
                }
            }
        }
    }
}

// ---------------------------------------------------------------------------
// GroupNorm (unchanged)
// ---------------------------------------------------------------------------
__global__ void gn_partial_kernel(const float* __restrict__ y)
{
    const int bid = blockIdx.x;
    const int bg = bid >> 5, sl = bid & 31;
    const int t = threadIdx.x;
    const float4* p = reinterpret_cast<const float4*>(
        y + (size_t)bg * ((kCOUT / kG) * kH * kW) + sl * 8192);

    double s = 0.0, q = 0.0;
    for (int i = t; i < 2048; i += 256) {
        float4 v = p[i];
        s += (double)v.x + (double)v.y + (double)v.z + (double)v.w;
        q += (double)v.x * v.x + (double)v.y * v.y +
             (double)v.z * v.z + (double)v.w * v.w;
    }
    __shared__ double sh_s[256], sh_q[256];
    sh_s[t] = s; sh_q[t] = q;
    __syncthreads();
    for (int off = 128; off > 0; off >>= 1) {
        if (t < off) { sh_s[t] += sh_s[t + off]; sh_q[t] += sh_q[t + off]; }
        __syncthreads();
    }
    if (t == 0) {
        g_part[(bg * 32 + sl) * 2 + 0] = sh_s[0];
        g_part[(bg * 32 + sl) * 2 + 1] = sh_q[0];
    }
}

__global__ void gn_final_kernel()
{
    const int bg = blockIdx.x;
    const int t = threadIdx.x;
    double s = g_part[(bg * 32 + t) * 2 + 0];
    double q = g_part[(bg * 32 + t) * 2 + 1];
    #pragma unroll
    for (int off = 16; off > 0; off >>= 1) {
        s += __shfl_down_sync(0xffffffffu, s, off);
        q += __shfl_down_sync(0xffffffffu, q, off);
    }
    if (t == 0) {
        const double N = (double)((kCOUT / kG) * kH * kW);
        double mean = s / N;
        double var  = q / N - mean * mean;
        g_stats[bg * 2 + 0] = (float)mean;
        g_stats[bg * 2 + 1] = (float)(1.0 / sqrt(var + 1e-5));
    }
}

__global__ void gn_apply_kernel(float* __restrict__ y,
                                const float* __restrict__ gamma,
                                const float* __restrict__ beta)
{
    const int idx4 = blockIdx.x * 256 + threadIdx.x;
    const int idx = idx4 * 4;
    const int c = (idx >> 14) & 127;
    const int bg = idx >> 18;
    const float mean = g_stats[bg * 2 + 0];
    const float rstd = g_stats[bg * 2 + 1];
    const float ga = gamma[c] * rstd;
    const float be = beta[c] - mean * ga;
    float4 v = *reinterpret_cast<float4*>(&y[idx]);
    v.x = v.x * ga + be;
    v.y = v.y * ga + be;
    v.z = v.z * ga + be;
    v.w = v.w * ga + be;
    *reinterpret_cast<float4*>(&y[idx]) = v;
}

// ---------------------------------------------------------------------------
// Launch
// ---------------------------------------------------------------------------
extern "C" void kernel_launch(void* const* d_in, const int* in_sizes, int n_in,
                              void* d_out, int out_size)
{
    const float* x     = (const float*)d_in[0];
    const float* W1    = (const float*)d_in[1];
    const float* b1    = (const float*)d_in[2];
    const float* W2    = (const float*)d_in[3];
    const float* b2    = (const float*)d_in[4];
    const float* Wr    = (const float*)d_in[5];
    const float* br    = (const float*)d_in[6];
    const float* Rw1   = (const float*)d_in[7];
    const float* Rb1   = (const float*)d_in[8];
    const float* Rw2   = (const float*)d_in[9];
    const float* Rb2   = (const float*)d_in[10];
    const float* gamma = (const float*)d_in[11];
    const float* beta  = (const float*)d_in[12];
    float* out = (float*)d_out;

    const int smem_bytes = 2 * BUF_WORDS * 4;   // 86784

    cudaFuncSetAttribute(conv1_all,
                         cudaFuncAttributeMaxDynamicSharedMemorySize, smem_bytes);
    cudaFuncSetAttribute(conv2_all,
                         cudaFuncAttributeMaxDynamicSharedMemorySize, smem_bytes);

    unsigned* w1h; cudaGetSymbolAddress((void**)&w1h, g_W1h);
    unsigned* w2h; cudaGetSymbolAddress((void**)&w2h, g_W2h);
    unsigned* wrh; cudaGetSymbolAddress((void**)&wrh, g_Wrh);

    prep_x_kernel<<<(kB * 4 * 8 * kH * kW) / 256, 256>>>(x);
    prep_w_all<<<2048, 256>>>(W1, W2, Wr);
    router_kernel<<<kB * kHp * kWp, 128>>>(x, Rw1, Rb1, Rw2, Rb2);

    conv1_all<<<dim3(4, 32, 64), 256, smem_bytes>>>(w1h, b1);
    conv2_all<<<dim3(4, 32, 8), 256, smem_bytes>>>(w2h, wrh, b2, br, out);

    gn_partial_kernel<<<kB * kG * 32, 256>>>(out);
    gn_final_kernel<<<kB * kG, 32>>>();
    gn_apply_kernel<<<(kB * kCOUT * kH * kW) / (256 * 4), 256>>>(out, gamma, beta);
}

// round 17
// speedup vs baseline: 1.9800x; 1.0097x over previous
#include <cuda_runtime.h>
#include <cuda_fp16.h>

// ---------------------------------------------------------------------------
// PCELayer R17: fp16 m16n8k16 convs, 128-thread CTAs.
// Warp tile 64co x (32x x 2y): 4 LDS.128 A + 8 LDS.64 B -> 32 MMA
// = 1.0 smem wavefront per MMA (R16 was 1.5; L1 was the binding pipe at 77%).
// ---------------------------------------------------------------------------

#define kB    8
#define kCIN  64
#define kCOUT 128
#define kH    128
#define kW    128
#define kE    8
#define kHp   8
#define kWp   8
#define kHID  128
#define kGCH  80
#define kG    8

// scratch
__device__ unsigned g_xh [kB * 4 * 8 * kH * kW];          // x f16x2 pair-planes
__device__ unsigned g_h1h[kE * kB * 8 * 8 * kH * kW];     // h1 f16x2 pair-planes
__device__ unsigned g_W1h[kE * 4 * 9216];                 // A images (f16x2)
__device__ unsigned g_W2h[kE * 8 * 9216];
__device__ unsigned g_Wrh[kE * 4 * 1024];
__device__ float    g_gates[kB * kHp * kWp * kE];
__device__ double   g_part[kB * kG * 32 * 2];
__device__ float    g_stats[kB * kG * 2];

#define CTA_THREADS 128

// ---------------------------------------------------------------------------
// helpers
// ---------------------------------------------------------------------------
__device__ __forceinline__ unsigned packh2(float lo, float hi) {
    __half2 h = __halves2half2(__float2half_rn(lo), __float2half_rn(hi));
    return *reinterpret_cast<unsigned*>(&h);
}

__device__ __forceinline__ void mma_f16(float acc[4], unsigned a0, unsigned a1,
                                        unsigned a2, unsigned a3,
                                        unsigned b0, unsigned b1) {
    asm volatile(
        "mma.sync.aligned.m16n8k16.row.col.f32.f16.f16.f32 "
        "{%0,%1,%2,%3}, {%4,%5,%6,%7}, {%8,%9}, {%0,%1,%2,%3};\n"
        : "+f"(acc[0]), "+f"(acc[1]), "+f"(acc[2]), "+f"(acc[3])
        : "r"(a0), "r"(a1), "r"(a2), "r"(a3), "r"(b0), "r"(b1));
}

__device__ __forceinline__ void cp_async16(unsigned* dst, const void* src) {
    unsigned d = (unsigned)__cvta_generic_to_shared(dst);
    asm volatile("cp.async.cg.shared.global [%0], [%1], 16;" :: "r"(d), "l"(src));
}
__device__ __forceinline__ void cp_async4z(unsigned* dst, const void* src, bool ok) {
    unsigned d = (unsigned)__cvta_generic_to_shared(dst);
    int sz = ok ? 4 : 0;
    asm volatile("cp.async.ca.shared.global [%0], [%1], 4, %2;" :: "r"(d), "l"(src), "r"(sz));
}
__device__ __forceinline__ void cp_commit() {
    asm volatile("cp.async.commit_group;");
}
template <int N>
__device__ __forceinline__ void cp_wait() {
    asm volatile("cp.async.wait_group %0;" :: "n"(N));
}

// ---------------------------------------------------------------------------
// Prep (unchanged from R16).
// x pair-planes: g_xh[((b*4+chunk)*8+slot)*16384 + pix], slot s -> pair
//   m = (s>>1) + (s&1)*4, word = f16x2(x[ch m], x[ch m+8]).
// A image per (chunk, tap): [mtile 8][lane 32][j 4].
// ---------------------------------------------------------------------------
__global__ void prep_x_kernel(const float* __restrict__ x) {
    int idx = blockIdx.x * 256 + threadIdx.x;
    int b = idx >> 19;
    int r = idx & 524287;
    int chunk = r >> 17;
    int r2 = r & 131071;
    int slot = r2 >> 14;
    int pix = r2 & 16383;
    int m = (slot >> 1) + (slot & 1) * 4;
    int ch0 = chunk * 16 + m;
    g_xh[idx] = packh2(x[(b * kCIN + ch0) * 16384 + pix],
                       x[(b * kCIN + ch0 + 8) * 16384 + pix]);
}

__device__ __forceinline__ unsigned perm_w3x3(const float* W, int CIN, int e, int r) {
    int chunk = r / 9216;
    int r2 = r - chunk * 9216;
    int tap = r2 >> 10;
    int r3 = r2 & 1023;
    int mt = r3 >> 7;
    int lane = (r3 >> 2) & 31;
    int j = r3 & 3;
    int row = mt * 16 + (lane >> 2) + (j & 1) * 8;
    int pair = (lane & 3) + ((j >> 1) << 2);
    int ci0 = chunk * 16 + pair;
    const float* wp = W + ((size_t)(e * 128 + row) * CIN) * 9 + tap;
    return packh2(wp[ci0 * 9], wp[(ci0 + 8) * 9]);
}

__global__ void prep_w_all(const float* __restrict__ W1,
                           const float* __restrict__ W2,
                           const float* __restrict__ Wr)
{
    const int N1 = kE * 4 * 9216;
    const int N2 = kE * 8 * 9216;
    const int N3 = kE * 4 * 1024;
    for (int idx = blockIdx.x * 256 + threadIdx.x; idx < N1 + N2 + N3;
         idx += gridDim.x * 256) {
        if (idx < N1) {
            int e = idx / 36864;
            g_W1h[idx] = perm_w3x3(W1, kCIN, e, idx - e * 36864);
        } else if (idx < N1 + N2) {
            int i2 = idx - N1;
            int e = i2 / 73728;
            g_W2h[i2] = perm_w3x3(W2, kCOUT, e, i2 - e * 73728);
        } else {
            int i3 = idx - N1 - N2;
            int e = i3 >> 12;
            int r = i3 & 4095;
            int chunk = r >> 10;
            int r3 = r & 1023;
            int mt = r3 >> 7;
            int lane = (r3 >> 2) & 31;
            int j = r3 & 3;
            int row = mt * 16 + (lane >> 2) + (j & 1) * 8;
            int pair = (lane & 3) + ((j >> 1) << 2);
            int ci0 = chunk * 16 + pair;
            g_Wrh[i3] = packh2(Wr[(e * 128 + row) * kCIN + ci0],
                               Wr[(e * 128 + row) * kCIN + ci0 + 8]);
        }
    }
}

// ---------------------------------------------------------------------------
// Router (unchanged)
// ---------------------------------------------------------------------------
__global__ void router_kernel(const float* __restrict__ x,
                              const float* __restrict__ Rw1,
                              const float* __restrict__ Rb1,
                              const float* __restrict__ Rw2,
                              const float* __restrict__ Rb2)
{
    __shared__ float s_g[kGCH];
    __shared__ float s_h[kHID];
    __shared__ float s_l[kE];

    const int blk = blockIdx.x;
    const int b  = blk >> 6;
    const int hp = (blk >> 3) & 7;
    const int wp = blk & 7;
    const int t  = threadIdx.x;

    if (t < 64) {
        const float* xp = x + ((b * kCIN + t) * kH + hp * 16) * kW + wp * 16;
        float s = 0.f;
        for (int r = 0; r < 16; r++) {
            const float4* rp = reinterpret_cast<const float4*>(xp + r * kW);
            #pragma unroll
            for (int c4 = 0; c4 < 4; c4++) {
                float4 v = rp[c4];
                s += v.x + v.y + v.z + v.w;
            }
        }
        s_g[t] = s * (1.f / 256.f);
    } else if (t < 80) {
        int k = t - 64;
        int f = k & 3;
        int kind = k >> 2;
        float freq = (float)(1 << f) * 3.14159265358979323846f;
        float coord = (kind < 2) ? ((hp + 0.5f) / 8.0f) : ((wp + 0.5f) / 8.0f);
        float a = coord * freq;
        s_g[t] = (kind & 1) ? cosf(a) : sinf(a);
    }
    __syncthreads();

    {
        float hsum = Rb1[t];
        #pragma unroll 4
        for (int c = 0; c < kGCH; c++) hsum = fmaf(s_g[c], Rw1[c * kHID + t], hsum);
        s_h[t] = fmaxf(hsum, 0.f);
    }
    __syncthreads();

    if (t < kE) {
        float l = Rb2[t];
        #pragma unroll 4
        for (int d = 0; d < kHID; d++) l = fmaf(s_h[d], Rw2[d * kE + t], l);
        s_l[t] = l;
    }
    __syncthreads();

    if (t == 0) {
        float m = s_l[0];
        #pragma unroll
        for (int e = 1; e < kE; e++) m = fmaxf(m, s_l[e]);
        float ex[kE];
        float ssum = 0.f;
        #pragma unroll
        for (int e = 0; e < kE; e++) { ex[e] = expf(s_l[e] - m); ssum += ex[e]; }
        float inv = 1.f / ssum;
        #pragma unroll
        for (int e = 0; e < kE; e++)
            g_gates[((b * kHp + hp) * kWp + wp) * kE + e] = ex[e] * inv;
    }
}

// ---------------------------------------------------------------------------
// Conv tiling: CTA 128co x (32x x 4y), 128 thr, 4 warps: wm=w>>1, wq=w&1.
// Warp: 64co x (32x x 2y). Per tap: 4 LDS.128 A + 8 LDS.64 B -> 32 MMA.
// In-tile smem: pixel-major, 8 f16x2 words per pixel, rows 6, cols 34.
// ---------------------------------------------------------------------------
#define W_WORDS   9216
#define IN_WORDS  1632
#define BUF_WORDS (W_WORDS + IN_WORDS)   // 10848 words = 43392 B

__device__ __forceinline__ void stage_job(unsigned* dyn, int bufi,
                                          const unsigned* __restrict__ srcw,
                                          int plane0,
                                          const unsigned* __restrict__ wsrc, int wn,
                                          int gy0, int gx0, int t)
{
    unsigned* bw  = dyn + bufi * BUF_WORDS;
    unsigned* bin = bw + W_WORDS;
    for (int i = t; i < wn / 4; i += CTA_THREADS)
        cp_async16(bw + i * 4, wsrc + i * 4);
    for (int idx = t; idx < IN_WORDS; idx += CTA_THREADS) {
        int pp  = idx / 204;
        int rem = idx - pp * 204;
        int row = rem / 34;
        int col = rem - row * 34;
        int gy = gy0 + row - 1;
        int gx = gx0 + col - 1;
        bool ok = ((unsigned)gy < (unsigned)kH) && ((unsigned)gx < (unsigned)kW);
        const unsigned* sp = srcw + (size_t)(plane0 + pp) * 16384
                           + (ok ? (gy * kW + gx) : 0);
        cp_async4z(bin + ((row * 34 + col) << 3) + pp, sp, ok);
    }
    cp_commit();
}

__device__ __forceinline__ void mma_main(unsigned* dyn, int bufi, int wm, int wq,
                                         int g, int tin, int lane,
                                         float acc[2][4][4][4])
{
    unsigned* bw = dyn + bufi * BUF_WORDS;
    const uint4* aw = reinterpret_cast<const uint4*>(bw);
    const uint2* sinp = reinterpret_cast<const uint2*>(bw + W_WORDS);
    #pragma unroll
    for (int tap = 0; tap < 9; tap++) {
        const int dy = tap / 3, dx = tap % 3;
        uint4 A[4];
        #pragma unroll
        for (int mt = 0; mt < 4; mt++)
            A[mt] = aw[(tap * 8 + wm * 4 + mt) * 32 + lane];
        #pragma unroll
        for (int ro = 0; ro < 2; ro++) {
            const int row = wq * 2 + ro + dy;
            const uint2* rp = sinp + (row * 34 + dx + g) * 4 + tin;
            #pragma unroll
            for (int nt = 0; nt < 4; nt++) {
                uint2 b01 = rp[nt * 32];
                #pragma unroll
                for (int mt = 0; mt < 4; mt++)
                    mma_f16(acc[ro][mt][nt], A[mt].x, A[mt].y, A[mt].z, A[mt].w,
                            b01.x, b01.y);
            }
        }
    }
}

__device__ __forceinline__ void mma_res(unsigned* dyn, int bufi, int wm, int wq,
                                        int g, int tin, int lane,
                                        float acc[2][4][4][4])
{
    unsigned* bw = dyn + bufi * BUF_WORDS;
    const uint4* aw = reinterpret_cast<const uint4*>(bw);
    const uint2* sinp = reinterpret_cast<const uint2*>(bw + W_WORDS);
    uint4 A[4];
    #pragma unroll
    for (int mt = 0; mt < 4; mt++)
        A[mt] = aw[(wm * 4 + mt) * 32 + lane];
    #pragma unroll
    for (int ro = 0; ro < 2; ro++) {
        const int row = wq * 2 + ro + 1;
        const uint2* rp = sinp + (row * 34 + 1 + g) * 4 + tin;
        #pragma unroll
        for (int nt = 0; nt < 4; nt++) {
            uint2 b01 = rp[nt * 32];
            #pragma unroll
            for (int mt = 0; mt < 4; mt++)
                mma_f16(acc[ro][mt][nt], A[mt].x, A[mt].y, A[mt].z, A[mt].w,
                        b01.x, b01.y);
        }
    }
}

// ---------------------------------------------------------------------------
// conv1_all: grid (4, 32, 64), z = e*8 + b.  4 jobs (16 ci each).
// ---------------------------------------------------------------------------
__global__ void __launch_bounds__(CTA_THREADS)
conv1_all(const unsigned* __restrict__ w1h, const float* __restrict__ b1)
{
    extern __shared__ unsigned dyn[];
    const int t = threadIdx.x;
    const int lane = t & 31, w = t >> 5;
    const int g = lane >> 2, tin = lane & 3;
    const int wm = w >> 1, wq = w & 1;
    const int gx0 = blockIdx.x * 32, gy0 = blockIdx.y * 4;
    const int e = blockIdx.z >> 3, b = blockIdx.z & 7;

    const unsigned* wbase = w1h + (size_t)e * 4 * W_WORDS;

    float acc[2][4][4][4];
    #pragma unroll
    for (int ro = 0; ro < 2; ro++)
        #pragma unroll
        for (int mt = 0; mt < 4; mt++)
            #pragma unroll
            for (int nt = 0; nt < 4; nt++)
                #pragma unroll
                for (int u = 0; u < 4; u++) acc[ro][mt][nt][u] = 0.f;

    stage_job(dyn, 0, g_xh, (b * 4 + 0) * 8, wbase, W_WORDS, gy0, gx0, t);
    for (int j = 0; j < 4; j++) {
        if (j + 1 < 4) {
            stage_job(dyn, (j + 1) & 1, g_xh, (b * 4 + j + 1) * 8,
                      wbase + (j + 1) * W_WORDS, W_WORDS, gy0, gx0, t);
            cp_wait<1>();
        } else {
            cp_wait<0>();
        }
        __syncthreads();
        mma_main(dyn, j & 1, wm, wq, g, tin, lane, acc);
        __syncthreads();
    }

    const float* bias = b1 + e * kCOUT;
    const int slot = (g < 4) ? (2 * g) : (2 * (g - 4) + 1);
    #pragma unroll
    for (int ro = 0; ro < 2; ro++) {
        const int y = gy0 + wq * 2 + ro;
        #pragma unroll
        for (int mt = 0; mt < 4; mt++) {
            int co0 = wm * 64 + mt * 16 + g;
            int chunkc = wm * 4 + mt;
            float bb0 = bias[co0], bb1 = bias[co0 + 8];
            size_t base = ((size_t)((e * kB + b) * 8 + chunkc) * 8 + slot) * 16384
                        + y * kW;
            #pragma unroll
            for (int nt = 0; nt < 4; nt++) {
                int gx = gx0 + nt * 8 + tin * 2;
                uint2 o;
                o.x = packh2(fmaxf(acc[ro][mt][nt][0] + bb0, 0.f),
                             fmaxf(acc[ro][mt][nt][2] + bb1, 0.f));
                o.y = packh2(fmaxf(acc[ro][mt][nt][1] + bb0, 0.f),
                             fmaxf(acc[ro][mt][nt][3] + bb1, 0.f));
                *reinterpret_cast<uint2*>(&g_h1h[base + gx]) = o;
            }
        }
    }
}

// ---------------------------------------------------------------------------
// conv2_all: grid (4, 32, 8); flat 96-job pipeline.
// ---------------------------------------------------------------------------
__global__ void __launch_bounds__(CTA_THREADS)
conv2_all(const unsigned* __restrict__ w2h, const unsigned* __restrict__ wrh,
          const float* __restrict__ b2, const float* __restrict__ br,
          float* __restrict__ out)
{
    extern __shared__ unsigned dyn[];
    const int t = threadIdx.x;
    const int lane = t & 31, w = t >> 5;
    const int g = lane >> 2, tin = lane & 3;
    const int wm = w >> 1, wq = w & 1;
    const int gx0 = blockIdx.x * 32, gy0 = blockIdx.y * 4;
    const int b = blockIdx.z;

    auto issue = [&](int J) {
        int e2 = J / 12;
        int j2 = J - e2 * 12;
        if (j2 < 8) {
            stage_job(dyn, J & 1, g_h1h, ((e2 * kB + b) * 8 + j2) * 8,
                      w2h + ((size_t)e2 * 8 + j2) * W_WORDS, W_WORDS, gy0, gx0, t);
        } else {
            int jr = j2 - 8;
            stage_job(dyn, J & 1, g_xh, (b * 4 + jr) * 8,
                      wrh + (size_t)e2 * 4096 + jr * 1024, 1024, gy0, gx0, t);
        }
    };

    float acc[2][4][4][4];
    #pragma unroll
    for (int ro = 0; ro < 2; ro++)
        #pragma unroll
        for (int mt = 0; mt < 4; mt++)
            #pragma unroll
            for (int nt = 0; nt < 4; nt++)
                #pragma unroll
                for (int u = 0; u < 4; u++) acc[ro][mt][nt][u] = 0.f;

    issue(0);
    for (int J = 0; J < kE * 12; J++) {
        const int e = J / 12;
        const int j = J - e * 12;
        if (J + 1 < kE * 12) {
            issue(J + 1);
            cp_wait<1>();
        } else {
            cp_wait<0>();
        }
        __syncthreads();
        if (j < 8) mma_main(dyn, J & 1, wm, wq, g, tin, lane, acc);
        else       mma_res (dyn, J & 1, wm, wq, g, tin, lane, acc);
        __syncthreads();

        if (j == 11) {
            #pragma unroll
            for (int ro = 0; ro < 2; ro++) {
                const int y = gy0 + wq * 2 + ro;
                const int prow = (b * kHp + (y >> 4)) * kWp;
                const float gateL = g_gates[(prow + ((gx0      ) >> 4)) * kE + e];
                const float gateR = g_gates[(prow + ((gx0 + 16) >> 4)) * kE + e];
                #pragma unroll
                for (int mt = 0; mt < 4; mt++) {
                    int co0 = wm * 64 + mt * 16 + g;
                    float bb0 = b2[e * kCOUT + co0] + br[e * kCOUT + co0];
                    float bb1 = b2[e * kCOUT + co0 + 8] + br[e * kCOUT + co0 + 8];
                    #pragma unroll
                    for (int nt = 0; nt < 4; nt++) {
                        const float gate = (nt < 2) ? gateL : gateR;
                        int gx = gx0 + nt * 8 + tin * 2;
                        float2 o0, o1;
                        o0.x = fmaxf(acc[ro][mt][nt][0] + bb0, 0.f) * gate;
                        o0.y = fmaxf(acc[ro][mt][nt][1] + bb0, 0.f) * gate;
                        o1.x = fmaxf(acc[ro][mt][nt][2] + bb1, 0.f) * gate;
                        o1.y = fmaxf(acc[ro][mt][nt][3] + bb1, 0.f) * gate;
                        float2* p0 = reinterpret_cast<float2*>(
                            &out[((b * kCOUT + co0    ) * kH + y) * kW + gx]);
                        float2* p1 = reinterpret_cast<float2*>(
                            &out[((b * kCOUT + co0 + 8) * kH + y) * kW + gx]);
                        if (e != 0) {
                            float2 v0 = *p0, v1 = *p1;
                            o0.x += v0.x; o0.y += v0.y;
                            o1.x += v1.x; o1.y += v1.y;
                        }
                        *p0 = o0;
                        *p1 = o1;
                        acc[ro][mt][nt][0] = 0.f; acc[ro][mt][nt][1] = 0.f;
                        acc[ro][mt][nt][2] = 0.f; acc[ro][mt][nt][3] = 0.f;
                    }
                }
            }
        }
    }
}

// ---------------------------------------------------------------------------
// GroupNorm (unchanged)
// ---------------------------------------------------------------------------
__global__ void gn_partial_kernel(const float* __restrict__ y)
{
    const int bid = blockIdx.x;
    const int bg = bid >> 5, sl = bid & 31;
    const int t = threadIdx.x;
    const float4* p = reinterpret_cast<const float4*>(
        y + (size_t)bg * ((kCOUT / kG) * kH * kW) + sl * 8192);

    double s = 0.0, q = 0.0;
    for (int i = t; i < 2048; i += 256) {
        float4 v = p[i];
        s += (double)v.x + (double)v.y + (double)v.z + (double)v.w;
        q += (double)v.x * v.x + (double)v.y * v.y +
             (double)v.z * v.z + (double)v.w * v.w;
    }
    __shared__ double sh_s[256], sh_q[256];
    sh_s[t] = s; sh_q[t] = q;
    __syncthreads();
    for (int off = 128; off > 0; off >>= 1) {
        if (t < off) { sh_s[t] += sh_s[t + off]; sh_q[t] += sh_q[t + off]; }
        __syncthreads();
    }
    if (t == 0) {
        g_part[(bg * 32 + sl) * 2 + 0] = sh_s[0];
        g_part[(bg * 32 + sl) * 2 + 1] = sh_q[0];
    }
}

__global__ void gn_final_kernel()
{
    const int bg = blockIdx.x;
    const int t = threadIdx.x;
    double s = g_part[(bg * 32 + t) * 2 + 0];
    double q = g_part[(bg * 32 + t) * 2 + 1];
    #pragma unroll
    for (int off = 16; off > 0; off >>= 1) {
        s += __shfl_down_sync(0xffffffffu, s, off);
        q += __shfl_down_sync(0xffffffffu, q, off);
    }
    if (t == 0) {
        const double N = (double)((kCOUT / kG) * kH * kW);
        double mean = s / N;
        double var  = q / N - mean * mean;
        g_stats[bg * 2 + 0] = (float)mean;
        g_stats[bg * 2 + 1] = (float)(1.0 / sqrt(var + 1e-5));
    }
}

__global__ void gn_apply_kernel(float* __restrict__ y,
                                const float* __restrict__ gamma,
                                const float* __restrict__ beta)
{
    const int idx4 = blockIdx.x * 256 + threadIdx.x;
    const int idx = idx4 * 4;
    const int c = (idx >> 14) & 127;
    const int bg = idx >> 18;
    const float mean = g_stats[bg * 2 + 0];
    const float rstd = g_stats[bg * 2 + 1];
    const float ga = gamma[c] * rstd;
    const float be = beta[c] - mean * ga;
    float4 v = *reinterpret_cast<float4*>(&y[idx]);
    v.x = v.x * ga + be;
    v.y = v.y * ga + be;
    v.z = v.z * ga + be;
    v.w = v.w * ga + be;
    *reinterpret_cast<float4*>(&y[idx]) = v;
}

// ---------------------------------------------------------------------------
// Launch
// ---------------------------------------------------------------------------
extern "C" void kernel_launch(void* const* d_in, const int* in_sizes, int n_in,
                              void* d_out, int out_size)
{
    const float* x     = (const float*)d_in[0];
    const float* W1    = (const float*)d_in[1];
    const float* b1    = (const float*)d_in[2];
    const float* W2    = (const float*)d_in[3];
    const float* b2    = (const float*)d_in[4];
    const float* Wr    = (const float*)d_in[5];
    const float* br    = (const float*)d_in[6];
    const float* Rw1   = (const float*)d_in[7];
    const float* Rb1   = (const float*)d_in[8];
    const float* Rw2   = (const float*)d_in[9];
    const float* Rb2   = (const float*)d_in[10];
    const float* gamma = (const float*)d_in[11];
    const float* beta  = (const float*)d_in[12];
    float* out = (float*)d_out;

    const int smem_bytes = 2 * BUF_WORDS * 4;   // 86784

    cudaFuncSetAttribute(conv1_all,
                         cudaFuncAttributeMaxDynamicSharedMemorySize, smem_bytes);
    cudaFuncSetAttribute(conv2_all,
                         cudaFuncAttributeMaxDynamicSharedMemorySize, smem_bytes);

    unsigned* w1h; cudaGetSymbolAddress((void**)&w1h, g_W1h);
    unsigned* w2h; cudaGetSymbolAddress((void**)&w2h, g_W2h);
    unsigned* wrh; cudaGetSymbolAddress((void**)&wrh, g_Wrh);

    prep_x_kernel<<<(kB * 4 * 8 * kH * kW) / 256, 256>>>(x);
    prep_w_all<<<2048, 256>>>(W1, W2, Wr);
    router_kernel<<<kB * kHp * kWp, 128>>>(x, Rw1, Rb1, Rw2, Rb2);

    conv1_all<<<dim3(4, 32, 64), CTA_THREADS, smem_bytes>>>(w1h, b1);
    conv2_all<<<dim3(4, 32, 8), CTA_THREADS, smem_bytes>>>(w2h, wrh, b2, br, out);

    gn_partial_kernel<<<kB * kG * 32, 256>>>(out);
    gn_final_kernel<<<kB * kG, 32>>>();
    gn_apply_kernel<<<(kB * kCOUT * kH * kW) / (256 * 4), 256>>>(out, gamma, beta);
}